// round 3
// baseline (speedup 1.0000x reference)
#include <cuda_runtime.h>
#include <cuda_bf16.h>
#include <stdint.h>

// Scatter-mean via counting-sort + gather (no atomics in the hot loop).
// Pipeline: detect id dtype -> init (zero counts, iota ids) -> histogram ->
//           block scan (offsets) -> build permutation -> gather+normalize.
// Fallback to the direct-atomic path for shapes exceeding static scratch.

#define MAX_NODES (1 << 20)
#define PERM_CAP  (1 << 21)

__device__ int g_is64;
__device__ int g_count[MAX_NODES];
__device__ int g_start[MAX_NODES];
__device__ int g_cursor[MAX_NODES];
__device__ int g_perm[PERM_CAP];
__device__ float g_fcounts[MAX_NODES];   // fallback path only

// ---------- dtype detect ----------
__global__ void detect_kernel(const unsigned int* __restrict__ words, int M) {
    __shared__ int any_nonzero;
    if (threadIdx.x == 0) any_nonzero = 0;
    __syncthreads();
    int n = M < 4096 ? M : 4096;
    for (int i = threadIdx.x; i < n; i += blockDim.x)
        if (words[2 * i + 1] != 0u) any_nonzero = 1;   // int64 high word
    __syncthreads();
    if (threadIdx.x == 0) g_is64 = any_nonzero ? 0 : 1;
}

__device__ __forceinline__ int load_id(const void* ids, int i, bool is64) {
    return is64 ? (int)((const long long*)ids)[i] : ((const int*)ids)[i];
}

// ---------- fast path ----------
__global__ void init_kernel(float* __restrict__ ids_out, int N, int has_ids) {
    int i = blockIdx.x * blockDim.x + threadIdx.x;
    int stride = gridDim.x * blockDim.x;
    for (; i < N; i += stride) {
        g_count[i] = 0;
        if (has_ids) ids_out[i] = (float)i;
    }
}

__global__ void hist_kernel(const void* __restrict__ ids, int M) {
    bool is64 = g_is64;
    int i = blockIdx.x * blockDim.x + threadIdx.x;
    int stride = gridDim.x * blockDim.x;
    for (; i < M; i += stride)
        atomicAdd(&g_count[load_id(ids, i, is64)], 1);
}

// Single-block exclusive scan over N counts -> g_start / g_cursor.
__global__ void scan_kernel(int N) {
    const int T = 1024;
    __shared__ int wsum[32];
    int tid = threadIdx.x;
    int per = (N + T - 1) / T;
    int b = tid * per;
    int e = b + per; if (e > N) e = N;
    int s = 0;
    for (int i = b; i < e; i++) s += g_count[i];
    int lane = tid & 31, warp = tid >> 5;
    int x = s;
    #pragma unroll
    for (int o = 1; o < 32; o <<= 1) {
        int y = __shfl_up_sync(0xffffffffu, x, o);
        if (lane >= o) x += y;
    }
    if (lane == 31) wsum[warp] = x;
    __syncthreads();
    if (warp == 0) {
        int w = wsum[lane];
        #pragma unroll
        for (int o = 1; o < 32; o <<= 1) {
            int y = __shfl_up_sync(0xffffffffu, w, o);
            if (lane >= o) w += y;
        }
        wsum[lane] = w;
    }
    __syncthreads();
    int excl = x - s + (warp > 0 ? wsum[warp - 1] : 0);
    int run = excl;
    for (int i = b; i < e; i++) {
        int c = g_count[i];
        g_start[i]  = run;
        g_cursor[i] = run;
        run += c;
    }
}

__global__ void build_perm_kernel(const void* __restrict__ ids, int M) {
    bool is64 = g_is64;
    int i = blockIdx.x * blockDim.x + threadIdx.x;
    int stride = gridDim.x * blockDim.x;
    for (; i < M; i += stride) {
        int id = load_id(ids, i, is64);
        int pos = atomicAdd(&g_cursor[id], 1);
        g_perm[pos] = i;
    }
}

// One warp per node; D == 128 specialization (32 float4 per row, 1 per lane).
// Permutation index is prefetched one iteration ahead so the row loads pipeline.
__global__ void gather_kernel(const float4* __restrict__ msgs4,
                              float* __restrict__ out, int N) {
    int gw   = (blockIdx.x * blockDim.x + threadIdx.x) >> 5;
    int lane = threadIdx.x & 31;
    if (gw >= N) return;

    int cnt   = g_count[gw];
    int start = g_start[gw];
    float4 acc = make_float4(0.f, 0.f, 0.f, 0.f);

    if (cnt > 0) {
        int idx  = g_perm[start];
        int idxn = (cnt > 1) ? g_perm[start + 1] : 0;
        float4 v = __ldg(&msgs4[(size_t)idx * 32 + lane]);
        for (int j = 1; j < cnt; j++) {
            int idxn2 = (j + 1 < cnt) ? g_perm[start + j + 1] : 0;
            float4 v2 = __ldg(&msgs4[(size_t)idxn * 32 + lane]);
            acc.x += v.x; acc.y += v.y; acc.z += v.z; acc.w += v.w;
            v = v2; idxn = idxn2;
        }
        acc.x += v.x; acc.y += v.y; acc.z += v.z; acc.w += v.w;
    }

    float inv = (cnt > 0) ? (1.0f / (float)cnt) : 0.0f;
    acc.x *= inv; acc.y *= inv; acc.z *= inv; acc.w *= inv;
    ((float4*)out)[(size_t)gw * 32 + lane] = acc;
}

// ---------- fallback path (generic D / oversized shapes) ----------
__device__ __forceinline__ void red_add_v4(float* addr, float4 v) {
    asm volatile("red.global.add.v4.f32 [%0], {%1, %2, %3, %4};"
                 :: "l"(addr), "f"(v.x), "f"(v.y), "f"(v.z), "f"(v.w) : "memory");
}
__device__ __forceinline__ void red_add_f32(float* addr, float v) {
    asm volatile("red.global.add.f32 [%0], %1;"
                 :: "l"(addr), "f"(v) : "memory");
}

__global__ void fb_init_kernel(float* __restrict__ sums, float* __restrict__ ids_out,
                               int N, int D, int has_ids) {
    long long total = (long long)N * D;
    for (long long i = blockIdx.x * (long long)blockDim.x + threadIdx.x;
         i < total; i += (long long)gridDim.x * blockDim.x)
        sums[i] = 0.f;
    for (long long i = blockIdx.x * (long long)blockDim.x + threadIdx.x;
         i < N; i += (long long)gridDim.x * blockDim.x) {
        if (i < MAX_NODES) g_fcounts[i] = 0.f;
        if (has_ids) ids_out[i] = (float)i;
    }
}

__global__ void fb_scatter_kernel(const void* __restrict__ ids,
                                  const float* __restrict__ msgs,
                                  float* __restrict__ sums, int M, int D) {
    int gwarp = (blockIdx.x * blockDim.x + threadIdx.x) >> 5;
    int lane  = threadIdx.x & 31;
    if (gwarp >= M) return;
    int id = load_id(ids, gwarp, g_is64 != 0);
    const float* row = msgs + (size_t)gwarp * D;
    float* dst = sums + (size_t)id * D;
    for (int c = lane * 4; c + 3 < D; c += 128)
        red_add_v4(dst + c, *(const float4*)(row + c));
    for (int c = (D / 4) * 4 + lane; c < D; c += 32)
        red_add_f32(dst + c, row[c]);
    if (lane == 0) red_add_f32(&g_fcounts[id], 1.0f);
}

__global__ void fb_normalize_kernel(float* __restrict__ sums, int N, int D) {
    long long total = (long long)N * D;
    for (long long i = blockIdx.x * (long long)blockDim.x + threadIdx.x;
         i < total; i += (long long)gridDim.x * blockDim.x) {
        int row = (int)(i / D);
        float inv = 1.0f / fmaxf(g_fcounts[row], 1.0f);
        sums[i] *= inv;
    }
}

extern "C" void kernel_launch(void* const* d_in, const int* in_sizes, int n_in,
                              void* d_out, int out_size) {
    const void*  ids  = d_in[0];
    const float* msgs = (const float*)d_in[1];

    int M = in_sizes[0];
    int D = in_sizes[1] / M;   // 128

    int N, has_ids;
    if (out_size % (D + 1) == 0) { N = out_size / (D + 1); has_ids = 1; }
    else                          { N = out_size / D;       has_ids = 0; }

    float* out     = (float*)d_out;
    float* ids_out = out;
    float* sums    = has_ids ? (out + N) : out;

    detect_kernel<<<1, 256>>>((const unsigned int*)ids, M);

    bool fast = (D == 128) && (N <= MAX_NODES) && (M <= PERM_CAP);

    if (fast) {
        {
            int blocks = (N + 255) / 256; if (blocks > 2048) blocks = 2048;
            init_kernel<<<blocks, 256>>>(ids_out, N, has_ids);
        }
        {
            int blocks = (M + 255) / 256; if (blocks > 2048) blocks = 2048;
            hist_kernel<<<blocks, 256>>>(ids, M);
        }
        scan_kernel<<<1, 1024>>>(N);
        {
            int blocks = (M + 255) / 256; if (blocks > 2048) blocks = 2048;
            build_perm_kernel<<<blocks, 256>>>(ids, M);
        }
        {
            long long threads = (long long)N * 32;
            int blocks = (int)((threads + 255) / 256);
            gather_kernel<<<blocks, 256>>>((const float4*)msgs, sums, N);
        }
    } else {
        {
            long long total = (long long)N * D;
            int blocks = (int)((total + 255) / 256); if (blocks > 4096) blocks = 4096;
            fb_init_kernel<<<blocks, 256>>>(sums, ids_out, N, D, has_ids);
        }
        {
            long long threads = (long long)M * 32;
            int blocks = (int)((threads + 255) / 256);
            fb_scatter_kernel<<<blocks, 256>>>(ids, msgs, sums, M, D);
        }
        {
            long long total = (long long)N * D;
            int blocks = (int)((total + 255) / 256); if (blocks > 4096) blocks = 4096;
            fb_normalize_kernel<<<blocks, 256>>>(sums, N, D);
        }
    }
}

// round 4
// speedup vs baseline: 1.4916x; 1.4916x over previous
#include <cuda_runtime.h>
#include <cuda_bf16.h>
#include <stdint.h>

// Scatter-mean via counting-sort + gather (no atomics in the hot loop).
// Pipeline: detect id dtype -> init -> histogram -> 3-stage parallel scan ->
//           build permutation -> gather+normalize.
// Fallback to a direct-atomic path for shapes exceeding static scratch.

#define MAX_NODES (1 << 20)
#define PERM_CAP  (1 << 21)
#define SCAN_TILE 4096
#define MAX_SCAN_BLOCKS ((MAX_NODES + SCAN_TILE - 1) / SCAN_TILE)

__device__ int g_is64;
__device__ int g_count[MAX_NODES];
__device__ int g_start[MAX_NODES];
__device__ int g_cursor[MAX_NODES];
__device__ int g_perm[PERM_CAP];
__device__ int g_bsum[MAX_SCAN_BLOCKS];
__device__ int g_boff[MAX_SCAN_BLOCKS];
__device__ float g_fcounts[MAX_NODES];   // fallback path only

// ---------- dtype detect ----------
__global__ void detect_kernel(const unsigned int* __restrict__ words, int M) {
    __shared__ int any_nonzero;
    if (threadIdx.x == 0) any_nonzero = 0;
    __syncthreads();
    int n = M < 4096 ? M : 4096;
    for (int i = threadIdx.x; i < n; i += blockDim.x)
        if (words[2 * i + 1] != 0u) any_nonzero = 1;   // int64 high word
    __syncthreads();
    if (threadIdx.x == 0) g_is64 = any_nonzero ? 0 : 1;
}

__device__ __forceinline__ int load_id(const void* ids, int i, bool is64) {
    return is64 ? (int)((const long long*)ids)[i] : ((const int*)ids)[i];
}

// ---------- fast path ----------
__global__ void init_kernel(float* __restrict__ ids_out, int N, int has_ids) {
    int i = blockIdx.x * blockDim.x + threadIdx.x;
    int stride = gridDim.x * blockDim.x;
    for (; i < N; i += stride) {
        g_count[i] = 0;
        if (has_ids) ids_out[i] = (float)i;
    }
}

__global__ void hist_kernel(const void* __restrict__ ids, int M) {
    bool is64 = g_is64;
    int i = blockIdx.x * blockDim.x + threadIdx.x;
    int stride = gridDim.x * blockDim.x;
    for (; i < M; i += stride)
        atomicAdd(&g_count[load_id(ids, i, is64)], 1);
}

// ----- 3-stage scan: partial sums -> scan of block sums -> final rescan -----
__global__ void scan_partial(int N) {
    __shared__ int wsum[32];
    int b = blockIdx.x, tid = threadIdx.x;
    int lane = tid & 31, warp = tid >> 5;
    int base = b * SCAN_TILE + tid * 4;
    int s = 0;
    #pragma unroll
    for (int k = 0; k < 4; k++) {
        int i = base + k;
        if (i < N) s += g_count[i];
    }
    #pragma unroll
    for (int o = 16; o > 0; o >>= 1) s += __shfl_down_sync(0xffffffffu, s, o);
    if (lane == 0) wsum[warp] = s;
    __syncthreads();
    if (warp == 0) {
        int w = wsum[lane];
        #pragma unroll
        for (int o = 16; o > 0; o >>= 1) w += __shfl_down_sync(0xffffffffu, w, o);
        if (lane == 0) g_bsum[b] = w;
    }
}

__global__ void scan_tops(int nb) {   // 1 block, nb <= 1024
    __shared__ int wsum[32];
    int tid = threadIdx.x, lane = tid & 31, warp = tid >> 5;
    int s = (tid < nb) ? g_bsum[tid] : 0;
    int x = s;
    #pragma unroll
    for (int o = 1; o < 32; o <<= 1) {
        int y = __shfl_up_sync(0xffffffffu, x, o);
        if (lane >= o) x += y;
    }
    if (lane == 31) wsum[warp] = x;
    __syncthreads();
    if (warp == 0) {
        int w = wsum[lane];
        #pragma unroll
        for (int o = 1; o < 32; o <<= 1) {
            int y = __shfl_up_sync(0xffffffffu, w, o);
            if (lane >= o) w += y;
        }
        wsum[lane] = w;
    }
    __syncthreads();
    if (tid < nb) g_boff[tid] = x - s + (warp > 0 ? wsum[warp - 1] : 0);
}

__global__ void scan_final(int N) {
    __shared__ int wsum[32];
    __shared__ int boff;
    int b = blockIdx.x, tid = threadIdx.x;
    int lane = tid & 31, warp = tid >> 5;
    if (tid == 0) boff = g_boff[b];
    int base = b * SCAN_TILE + tid * 4;
    int v[4]; int s = 0;
    #pragma unroll
    for (int k = 0; k < 4; k++) {
        int i = base + k;
        v[k] = (i < N) ? g_count[i] : 0;
        s += v[k];
    }
    int x = s;
    #pragma unroll
    for (int o = 1; o < 32; o <<= 1) {
        int y = __shfl_up_sync(0xffffffffu, x, o);
        if (lane >= o) x += y;
    }
    if (lane == 31) wsum[warp] = x;
    __syncthreads();
    if (warp == 0) {
        int w = wsum[lane];
        #pragma unroll
        for (int o = 1; o < 32; o <<= 1) {
            int y = __shfl_up_sync(0xffffffffu, w, o);
            if (lane >= o) w += y;
        }
        wsum[lane] = w;
    }
    __syncthreads();
    int run = x - s + (warp > 0 ? wsum[warp - 1] : 0) + boff;
    #pragma unroll
    for (int k = 0; k < 4; k++) {
        int i = base + k;
        if (i < N) {
            g_start[i]  = run;
            g_cursor[i] = run;
            run += v[k];
        }
    }
}

__global__ void build_perm_kernel(const void* __restrict__ ids, int M) {
    bool is64 = g_is64;
    int i = blockIdx.x * blockDim.x + threadIdx.x;
    int stride = gridDim.x * blockDim.x;
    for (; i < M; i += stride) {
        int id = load_id(ids, i, is64);
        int pos = atomicAdd(&g_cursor[id], 1);
        g_perm[pos] = i;
    }
}

// One warp per node; D == 128 specialization (32 float4 per row, 1 per lane).
__global__ void gather_kernel(const float4* __restrict__ msgs4,
                              float* __restrict__ out, int N) {
    int gw   = (blockIdx.x * blockDim.x + threadIdx.x) >> 5;
    int lane = threadIdx.x & 31;
    if (gw >= N) return;

    int cnt   = g_count[gw];
    int start = g_start[gw];
    float4 acc = make_float4(0.f, 0.f, 0.f, 0.f);

    if (cnt > 0) {
        int idx  = g_perm[start];
        int idxn = (cnt > 1) ? g_perm[start + 1] : 0;
        float4 v = __ldg(&msgs4[(size_t)idx * 32 + lane]);
        for (int j = 1; j < cnt; j++) {
            int idxn2 = (j + 1 < cnt) ? g_perm[start + j + 1] : 0;
            float4 v2 = __ldg(&msgs4[(size_t)idxn * 32 + lane]);
            acc.x += v.x; acc.y += v.y; acc.z += v.z; acc.w += v.w;
            v = v2; idxn = idxn2;
        }
        acc.x += v.x; acc.y += v.y; acc.z += v.z; acc.w += v.w;
    }

    float inv = (cnt > 0) ? (1.0f / (float)cnt) : 0.0f;
    acc.x *= inv; acc.y *= inv; acc.z *= inv; acc.w *= inv;
    ((float4*)out)[(size_t)gw * 32 + lane] = acc;
}

// ---------- fallback path (generic D / oversized shapes) ----------
__device__ __forceinline__ void red_add_v4(float* addr, float4 v) {
    asm volatile("red.global.add.v4.f32 [%0], {%1, %2, %3, %4};"
                 :: "l"(addr), "f"(v.x), "f"(v.y), "f"(v.z), "f"(v.w) : "memory");
}
__device__ __forceinline__ void red_add_f32(float* addr, float v) {
    asm volatile("red.global.add.f32 [%0], %1;"
                 :: "l"(addr), "f"(v) : "memory");
}

__global__ void fb_init_kernel(float* __restrict__ sums, float* __restrict__ ids_out,
                               int N, int D, int has_ids) {
    long long total = (long long)N * D;
    for (long long i = blockIdx.x * (long long)blockDim.x + threadIdx.x;
         i < total; i += (long long)gridDim.x * blockDim.x)
        sums[i] = 0.f;
    for (long long i = blockIdx.x * (long long)blockDim.x + threadIdx.x;
         i < N; i += (long long)gridDim.x * blockDim.x) {
        if (i < MAX_NODES) g_fcounts[i] = 0.f;
        if (has_ids) ids_out[i] = (float)i;
    }
}

__global__ void fb_scatter_kernel(const void* __restrict__ ids,
                                  const float* __restrict__ msgs,
                                  float* __restrict__ sums, int M, int D) {
    int gwarp = (blockIdx.x * blockDim.x + threadIdx.x) >> 5;
    int lane  = threadIdx.x & 31;
    if (gwarp >= M) return;
    int id = load_id(ids, gwarp, g_is64 != 0);
    const float* row = msgs + (size_t)gwarp * D;
    float* dst = sums + (size_t)id * D;
    for (int c = lane * 4; c + 3 < D; c += 128)
        red_add_v4(dst + c, *(const float4*)(row + c));
    for (int c = (D / 4) * 4 + lane; c < D; c += 32)
        red_add_f32(dst + c, row[c]);
    if (lane == 0) red_add_f32(&g_fcounts[id], 1.0f);
}

__global__ void fb_normalize_kernel(float* __restrict__ sums, int N, int D) {
    long long total = (long long)N * D;
    for (long long i = blockIdx.x * (long long)blockDim.x + threadIdx.x;
         i < total; i += (long long)gridDim.x * blockDim.x) {
        int row = (int)(i / D);
        float inv = 1.0f / fmaxf(g_fcounts[row], 1.0f);
        sums[i] *= inv;
    }
}

extern "C" void kernel_launch(void* const* d_in, const int* in_sizes, int n_in,
                              void* d_out, int out_size) {
    const void*  ids  = d_in[0];
    const float* msgs = (const float*)d_in[1];

    int M = in_sizes[0];
    int D = in_sizes[1] / M;   // 128

    int N, has_ids;
    if (out_size % (D + 1) == 0) { N = out_size / (D + 1); has_ids = 1; }
    else                          { N = out_size / D;       has_ids = 0; }

    float* out     = (float*)d_out;
    float* ids_out = out;
    float* sums    = has_ids ? (out + N) : out;

    detect_kernel<<<1, 256>>>((const unsigned int*)ids, M);

    int nb = (N + SCAN_TILE - 1) / SCAN_TILE;
    bool fast = (D == 128) && (N <= MAX_NODES) && (M <= PERM_CAP) && (nb <= 1024);

    if (fast) {
        {
            int blocks = (N + 255) / 256; if (blocks > 2048) blocks = 2048;
            init_kernel<<<blocks, 256>>>(ids_out, N, has_ids);
        }
        {
            int blocks = (M + 255) / 256; if (blocks > 2048) blocks = 2048;
            hist_kernel<<<blocks, 256>>>(ids, M);
        }
        scan_partial<<<nb, 1024>>>(N);
        scan_tops<<<1, 1024>>>(nb);
        scan_final<<<nb, 1024>>>(N);
        {
            int blocks = (M + 255) / 256; if (blocks > 2048) blocks = 2048;
            build_perm_kernel<<<blocks, 256>>>(ids, M);
        }
        {
            long long threads = (long long)N * 32;
            int blocks = (int)((threads + 255) / 256);
            gather_kernel<<<blocks, 256>>>((const float4*)msgs, sums, N);
        }
    } else {
        {
            long long total = (long long)N * D;
            int blocks = (int)((total + 255) / 256); if (blocks > 4096) blocks = 4096;
            fb_init_kernel<<<blocks, 256>>>(sums, ids_out, N, D, has_ids);
        }
        {
            long long threads = (long long)M * 32;
            int blocks = (int)((threads + 255) / 256);
            fb_scatter_kernel<<<blocks, 256>>>(ids, msgs, sums, M, D);
        }
        {
            long long total = (long long)N * D;
            int blocks = (int)((total + 255) / 256); if (blocks > 4096) blocks = 4096;
            fb_normalize_kernel<<<blocks, 256>>>(sums, N, D);
        }
    }
}